// round 15
// baseline (speedup 1.0000x reference)
#include <cuda_runtime.h>
#include <math.h>
#include <stdint.h>

#define B 128
#define T 512
#define E 256
#define H 256
#define DA 25
#define HEADS 5
#define V 2080

typedef unsigned long long ull;

// ---------------- device scratch (static, no allocs) ----------------
__device__ float g_P[(size_t)2 * V * 1024];        // [dir][v][4H]  17MB (L2-resident)
__device__ float g_hstate[2 * 2 * B * H];          // [buf][dir][slot][H]  (slot-indexed)
__device__ float g_Hc[(size_t)B * T * 2 * H];      // [b][t][512]; tail stale-but-finite, masked by A=0
__device__ float g_s[B * HEADS * T];               // [b][h][t]
__device__ float g_A[B * HEADS * T];               // [b][h][t]
__device__ float g_pp[B];
__device__ int g_perm[B];                          // rank -> batch (length desc)
__device__ int g_slen[B];                          // rank -> length

// fast, overflow-safe sigmoid/tanh via MUFU.EX2 path (__expf)
__device__ __forceinline__ float sigf(float x) {
    return 1.0f / (1.0f + __expf(-x));
}
__device__ __forceinline__ float tanhfast(float x) {
    float ax = fabsf(x);
    float e = __expf(2.0f * ax);
    float t = 1.0f - 2.0f / (e + 1.0f);
    return copysignf(t, x);
}

__device__ __forceinline__ ull pack2(float lo, float hi) {
    ull r; asm("mov.b64 %0, {%1,%2};" : "=l"(r) : "f"(lo), "f"(hi)); return r;
}
__device__ __forceinline__ void unpack2(ull v, float& lo, float& hi) {
    asm("mov.b64 {%0,%1}, %2;" : "=f"(lo), "=f"(hi) : "l"(v));
}
__device__ __forceinline__ ull fma2(ull a, ull b, ull c) {
    ull d; asm("fma.rn.f32x2 %0, %1, %2, %3;" : "=l"(d) : "l"(a), "l"(b), "l"(c)); return d;
}
__device__ __forceinline__ ull add2(ull a, ull b) {
    ull d; asm("add.rn.f32x2 %0, %1, %2;" : "=l"(d) : "l"(a), "l"(b)); return d;
}
__device__ __forceinline__ uint32_t smem_u32(const void* p) {
    return (uint32_t)__cvta_generic_to_shared(p);
}
__device__ __forceinline__ uint32_t mapa_u32(uint32_t addr, uint32_t rank) {
    uint32_t r; asm("mapa.shared::cluster.u32 %0, %1, %2;" : "=r"(r) : "r"(addr), "r"(rank));
    return r;
}
__device__ __forceinline__ void mbar_init(uint32_t addr, uint32_t count) {
    asm volatile("mbarrier.init.shared.b64 [%0], %1;" :: "r"(addr), "r"(count) : "memory");
}
__device__ __forceinline__ void mbar_arrive_remote(uint32_t addr) {
    asm volatile("mbarrier.arrive.release.cluster.shared::cluster.b64 _, [%0];" :: "r"(addr) : "memory");
}
__device__ __forceinline__ void mbar_wait(uint32_t mb, uint32_t phase) {
    uint32_t done;
    do {
        asm volatile(
            "{\n\t.reg .pred p;\n\t"
            "mbarrier.try_wait.parity.acquire.cluster.shared::cta.b64 p, [%1], %2, 0x989680;\n\t"
            "selp.b32 %0, 1, 0, p;\n\t}"
            : "=r"(done) : "r"(mb), "r"(phase) : "memory");
    } while (!done);
}
#define CLUSTER_SYNC() do { \
    asm volatile("barrier.cluster.arrive.aligned;" ::: "memory"); \
    asm volatile("barrier.cluster.wait.aligned;" ::: "memory"); \
} while (0)

// ---------------- init: zero h buffers ------------------------------
__global__ void k_init() {
    size_t i = (size_t)blockIdx.x * blockDim.x + threadIdx.x;
    size_t stride = (size_t)gridDim.x * blockDim.x;
    for (size_t p = i; p < (size_t)2 * 2 * B * H; p += stride) g_hstate[p] = 0.0f;
}

// ---------------- rank batches by length (descending, stable) -------
__global__ void k_perm(const int* __restrict__ lens) {
    __shared__ int Ls[B];
    int i = threadIdx.x;
    Ls[i] = lens[i];
    __syncthreads();
    int Li = Ls[i];
    int rank = 0;
    #pragma unroll 8
    for (int j = 0; j < B; j++) {
        int Lj = Ls[j];
        rank += (Lj > Li) || (Lj == Li && j < i);
    }
    g_perm[rank] = i;
    g_slen[rank] = Li;
}

// ---------------- vocab projection: P[d][v][n] = emb[v] . W_ih[n] + b[n]
__global__ void k_P(const float* __restrict__ emb,
                    const float* __restrict__ Wf, const float* __restrict__ bf,
                    const float* __restrict__ Wb, const float* __restrict__ bb)
{
    const int d = blockIdx.z;
    const float* __restrict__ Wih  = d ? Wb : Wf;
    const float* __restrict__ bias = d ? bb : bf;
    const int n0 = blockIdx.x * 64;
    const int m0 = blockIdx.y * 64;

    __shared__ float As[16][68];
    __shared__ float Bs[16][68];

    const int tid = threadIdx.x;
    const int r  = tid >> 2, kq = tid & 3;
    const int tx = tid & 15, ty = tid >> 4;
    int v = m0 + r; if (v >= V) v = 0;
    const float* __restrict__ Arow = emb + (size_t)v * E;
    const float* __restrict__ Brow = Wih + (size_t)(n0 + r) * E;

    float acc[4][4] = {};

    for (int k0 = 0; k0 < E; k0 += 16) {
        float4 av = *(const float4*)&Arow[k0 + kq * 4];
        float4 bv = *(const float4*)&Brow[k0 + kq * 4];
        As[kq * 4 + 0][r] = av.x; As[kq * 4 + 1][r] = av.y;
        As[kq * 4 + 2][r] = av.z; As[kq * 4 + 3][r] = av.w;
        Bs[kq * 4 + 0][r] = bv.x; Bs[kq * 4 + 1][r] = bv.y;
        Bs[kq * 4 + 2][r] = bv.z; Bs[kq * 4 + 3][r] = bv.w;
        __syncthreads();
        #pragma unroll
        for (int kk = 0; kk < 16; kk++) {
            float4 a  = *(const float4*)&As[kk][ty * 4];
            float4 b4 = *(const float4*)&Bs[kk][tx * 4];
            acc[0][0] = fmaf(a.x, b4.x, acc[0][0]); acc[0][1] = fmaf(a.x, b4.y, acc[0][1]);
            acc[0][2] = fmaf(a.x, b4.z, acc[0][2]); acc[0][3] = fmaf(a.x, b4.w, acc[0][3]);
            acc[1][0] = fmaf(a.y, b4.x, acc[1][0]); acc[1][1] = fmaf(a.y, b4.y, acc[1][1]);
            acc[1][2] = fmaf(a.y, b4.z, acc[1][2]); acc[1][3] = fmaf(a.y, b4.w, acc[1][3]);
            acc[2][0] = fmaf(a.z, b4.x, acc[2][0]); acc[2][1] = fmaf(a.z, b4.y, acc[2][1]);
            acc[2][2] = fmaf(a.z, b4.z, acc[2][2]); acc[2][3] = fmaf(a.z, b4.w, acc[2][3]);
            acc[3][0] = fmaf(a.w, b4.x, acc[3][0]); acc[3][1] = fmaf(a.w, b4.y, acc[3][1]);
            acc[3][2] = fmaf(a.w, b4.z, acc[3][2]); acc[3][3] = fmaf(a.w, b4.w, acc[3][3]);
        }
        __syncthreads();
    }

    float b0v = bias[n0 + tx * 4 + 0];
    float b1v = bias[n0 + tx * 4 + 1];
    float b2v = bias[n0 + tx * 4 + 2];
    float b3v = bias[n0 + tx * 4 + 3];
    const size_t pbase = (size_t)d * V * 1024;
    #pragma unroll
    for (int i = 0; i < 4; i++) {
        int m = m0 + ty * 4 + i;
        if (m < V) {
            float4 o;
            o.x = acc[i][0] + b0v; o.y = acc[i][1] + b1v;
            o.z = acc[i][2] + b2v; o.w = acc[i][3] + b3v;
            *(float4*)&g_P[pbase + (size_t)m * 1024 + n0 + tx * 4] = o;
        }
    }
}

// ---------------- persistent LSTM recurrence (cluster-mbarrier sync) --
// 128 blocks = 16 clusters of 8. Cluster = (dir, slot-group of 16 slots);
// CTA rank within cluster = j-tile (32 j). Chain sync = double-buffered
// cluster mbarriers: remote arrive (DSMEM, fire-and-forget) + local
// try_wait (60-90 cyc) replaces L2 counter release/poll. h data exchange
// stays via global memory + __ldcg staging (R12-proven) — NOT DSMEM.
// Slots length-sorted desc, dealt round-robin (rank = 8s+bg); nact(t)
// shrinks compute to the live prefix (identical across the cluster).
// Compute role: warp (kq 0..3, gh 0..1), lane (jcp 0..15, gl 0..1); thread
// owns W rows (g=2gh+gl, j=j0+2jcp, +1) over its 64-k slice in registers.
// Epilogue role: thread (slot 0..15, jp 0..15) -> 1 slot, j-pair.
__global__ void __launch_bounds__(256, 1) __cluster_dims__(8, 1, 1)
k_lstm(const float* __restrict__ Whf, const float* __restrict__ Whb,
       const int* __restrict__ lens, const int* __restrict__ wid)
{
    extern __shared__ float sm[];
    float* Hsh = sm;                       // [16][256] = 4096 floats (16 KB)
    float* Red = sm + 4096;                // [64 rows][132] = 8448 floats
    int*   slen16 = (int*)(sm + 12544);    // [16]
    // mbarriers at byte offsets 50240, 50248 (8-byte aligned)
    const uint32_t smb = smem_u32(sm);
    const uint32_t MB_OFF = 12560u * 4u;
    const uint32_t mb[2] = { smb + MB_OFF, smb + MB_OFF + 8 };

    const int tid = threadIdx.x;
    const int d   = blockIdx.x >> 6;
    const int rem = blockIdx.x & 63;
    const int jb  = rem & 7, bg = rem >> 3;    // consecutive bx = cluster = chain
    const int j0  = jb * 32, b0 = bg * 16;     // b0 = slot base
    const float* __restrict__ Whh = d ? Whb : Whf;
    const float* __restrict__ P   = g_P + (size_t)d * V * 1024;

    // ---- compute-role indices ----
    const int warp = tid >> 5, lane = tid & 31;
    const int kq = warp & 3, gh = warp >> 2;
    const int jcp = lane >> 1, gl = lane & 1;
    const int gc = gh * 2 + gl;

    // ---- W -> registers: 2 j-rows x 64 k, packed over k-pairs ----
    ull w2a[32], w2b[32];
    {
        const float2* wra = (const float2*)(Whh + (size_t)(gc * H + j0 + 2 * jcp)     * H + kq * 64);
        const float2* wrb = (const float2*)(Whh + (size_t)(gc * H + j0 + 2 * jcp + 1) * H + kq * 64);
        #pragma unroll
        for (int i = 0; i < 32; i++) {
            float2 va = __ldg(&wra[i]);
            float2 vb = __ldg(&wrb[i]);
            w2a[i] = pack2(va.x, va.y);
            w2b[i] = pack2(vb.x, vb.y);
        }
    }

    // ---- epilogue-role indices (slot bqs -> global rank 8bqs+bg) ----
    const int jp = tid & 15, bqs = tid >> 4;    // 16 x 16
    const int rankE = 8 * bqs + bg;
    const int bE = g_perm[rankE];               // true batch id
    const int LE = g_slen[rankE];
    const int jcol = j0 + jp * 2;
    if (tid < 16) slen16[tid] = g_slen[8 * tid + bg];
    if (tid == 0) { mbar_init(mb[0], 8); mbar_init(mb[1], 8); }
    __syncthreads();
    CLUSTER_SYNC();   // mbarriers initialized cluster-wide before any remote arrive

    // remote mbarrier base addresses for all 8 cluster ranks
    uint32_t mb_rem[8];
    #pragma unroll
    for (int r = 0; r < 8; r++) mb_rem[r] = mapa_u32(smb + MB_OFF, (uint32_t)r);

    const int maxlen = slen16[0];
    int nact = 16;
    float c0 = 0.f, c1 = 0.f;
    uint32_t ph[2] = { 0u, 0u };

    for (int t = 0; t < maxlen; t++) {
        // ---- shrink active prefix (sorted desc; identical across cluster) ----
        while (nact > 0 && slen16[nact - 1] <= t) nact--;
        const int rowcnt = (nact + 3) & ~3;
        const int bbn = (nact + 1) >> 1;

        // ---- px prefetch (epilogue role; L2-resident P) ----
        float2 px0, px1, px2, px3;
        int pos = 0;
        const bool vE = (t < LE);
        if (vE) {
            pos = d ? (LE - 1 - t) : t;
            const float2* p = (const float2*)(P + (size_t)wid[bE * T + pos] * 1024) + (j0 >> 1) + jp;
            px0 = __ldg(p); px1 = __ldg(p + 128); px2 = __ldg(p + 256); px3 = __ldg(p + 384);
        }

        // ---- wait for all 8 CTAs' h(t-1): local mbarrier (fast wakeup) ----
        const int rb = t & 1, wb = (t + 1) & 1;
        if (t > 0) { mbar_wait(mb[rb], ph[rb]); ph[rb] ^= 1u; }

        // ---- stage live h rows (slot-indexed, from L2) ----
        {
            const float* hsrc = g_hstate + ((size_t)(rb * 2 + d) * B + b0) * H;
            for (int i = tid; i < rowcnt * 64; i += 256) {
                int r = i >> 6, cc = i & 63;
                float4 hv = __ldcg((const float4*)(hsrc + r * H + cc * 4));
                *(float4*)&Hsh[r * 256 + cc * 4] = hv;
            }
        }
        __syncthreads();

        // ---- compute live slots: W in regs (2 j rows), h broadcast ----
        for (int bb = 0; bb < bbn; bb++) {
            const ulonglong2* r0 = (const ulonglong2*)(Hsh + (2 * bb) * 256 + kq * 64);
            const ulonglong2* r1 = (const ulonglong2*)(Hsh + (2 * bb + 1) * 256 + kq * 64);
            ull aA0 = 0, aA1 = 0, aB0 = 0, aB1 = 0;   // slot0/1 x j-even/odd (k-pair lanes)
            #pragma unroll
            for (int k4 = 0; k4 < 16; k4++) {
                ulonglong2 h0 = r0[k4];
                ulonglong2 h1 = r1[k4];
                aA0 = fma2(w2a[2 * k4],     h0.x, aA0);
                aA1 = fma2(w2b[2 * k4],     h0.x, aA1);
                aB0 = fma2(w2a[2 * k4],     h1.x, aB0);
                aB1 = fma2(w2b[2 * k4],     h1.x, aB1);
                aA0 = fma2(w2a[2 * k4 + 1], h0.y, aA0);
                aA1 = fma2(w2b[2 * k4 + 1], h0.y, aA1);
                aB0 = fma2(w2a[2 * k4 + 1], h1.y, aB0);
                aB1 = fma2(w2b[2 * k4 + 1], h1.y, aB1);
            }
            float xA0, yA0, xA1, yA1, xB0, yB0, xB1, yB1;
            unpack2(aA0, xA0, yA0); unpack2(aA1, xA1, yA1);
            unpack2(aB0, xB0, yB0); unpack2(aB1, xB1, yB1);
            // pack (j even, j odd) into one 8B store per slot
            *(ull*)&Red[((2 * bb)     * 4 + gc) * 132 + kq * 32 + jcp * 2] = pack2(xA0 + yA0, xA1 + yA1);
            *(ull*)&Red[((2 * bb + 1) * 4 + gc) * 132 + kq * 32 + jcp * 2] = pack2(xB0 + yB0, xB1 + yB1);
        }
        __syncthreads();

        // ---- epilogue: reduce over kq, gates, publish ----
        if (vE) {
            ull ag[4];
            #pragma unroll
            for (int g = 0; g < 4; g++) {
                const float* rr = Red + (size_t)(bqs * 4 + g) * 132 + jp * 2;
                ull v0 = *(const ull*)(rr);
                ull v1 = *(const ull*)(rr + 32);
                ull v2 = *(const ull*)(rr + 64);
                ull v3 = *(const ull*)(rr + 96);
                ag[g] = add2(add2(v0, v1), add2(v2, v3));
            }
            float gi0, gi1, gf0, gf1, gg0, gg1, go0, go1;
            unpack2(ag[0], gi0, gi1); unpack2(ag[1], gf0, gf1);
            unpack2(ag[2], gg0, gg1); unpack2(ag[3], go0, go1);
            float i0 = sigf (gi0 + px0.x), i1 = sigf (gi1 + px0.y);
            float f0 = sigf (gf0 + px1.x), f1 = sigf (gf1 + px1.y);
            float g0 = tanhfast(gg0 + px2.x), g1 = tanhfast(gg1 + px2.y);
            float o0 = sigf (go0 + px3.x), o1 = sigf (go1 + px3.y);
            c0 = f0 * c0 + i0 * g0;
            c1 = f1 * c1 + i1 * g1;
            float2 hv; hv.x = o0 * tanhfast(c0); hv.y = o1 * tanhfast(c1);
            // slot-indexed internal state; batch-indexed Hc output
            *(float2*)&g_hstate[((size_t)(wb * 2 + d) * B + b0 + bqs) * H + jcol] = hv;
            *(float2*)&g_Hc[((size_t)bE * T + pos) * (2 * H) + d * H + jcol] = hv;
        }

        // ---- arrive: bar.sync orders all threads' h stores before the
        //      release-arrive; one remote arrive per peer (tid<8) ----
        __syncthreads();
        if (tid < 8)
            mbar_arrive_remote(mb_rem[tid] + (uint32_t)(wb * 8));
    }

    CLUSTER_SYNC();   // no CTA exits while peers may still arrive on its mbarriers
}

// ---------------- attention scores: s = tanh(Hc W_s1^T) W_s2^T ------
__global__ void k_scores(const float* __restrict__ Ws1, const float* __restrict__ Ws2)
{
    extern __shared__ float s2[];
    float* Ws  = s2;            // 25*512 = 12800
    float* raw = s2 + 12800;    // 32*25 = 800
    float* usm = s2 + 13600;    // 800

    const int tid = threadIdx.x;
    const int b  = blockIdx.x >> 4;
    const int t0 = (blockIdx.x & 15) * 32;

    for (int i = tid; i < 12800; i += 512) Ws[i] = Ws1[i];
    __syncthreads();

    const int wp = tid >> 5, lane = tid & 31;
    float acc0[DA] = {}, acc1[DA] = {};
    const float* hc0 = g_Hc + ((size_t)b * T + t0 + wp * 2) * 512;
    #pragma unroll 4
    for (int kk = 0; kk < 16; kk++) {
        int k = lane + kk * 32;
        float h0 = hc0[k];
        float h1 = hc0[512 + k];
        #pragma unroll
        for (int a = 0; a < DA; a++) {
            float w = Ws[a * 512 + k];
            acc0[a] = fmaf(h0, w, acc0[a]);
            acc1[a] = fmaf(h1, w, acc1[a]);
        }
    }
    #pragma unroll
    for (int a = 0; a < DA; a++) {
        float v0 = acc0[a], v1 = acc1[a];
        #pragma unroll
        for (int off = 16; off; off >>= 1) {
            v0 += __shfl_xor_sync(0xffffffffu, v0, off);
            v1 += __shfl_xor_sync(0xffffffffu, v1, off);
        }
        if (lane == 0) {
            raw[(wp * 2 + 0) * DA + a] = v0;
            raw[(wp * 2 + 1) * DA + a] = v1;
        }
    }
    __syncthreads();
    for (int i = tid; i < 32 * DA; i += 512) usm[i] = tanhf(raw[i]);
    __syncthreads();
    if (tid < 32 * HEADS) {
        int r = tid / HEADS, h = tid % HEADS;
        float s = 0.f;
        #pragma unroll
        for (int a = 0; a < DA; a++) s = fmaf(usm[r * DA + a], __ldg(&Ws2[h * DA + a]), s);
        g_s[((size_t)b * HEADS + h) * T + t0 + r] = s;
    }
}

// ---------------- masked softmax over time, per (b,head) ------------
__global__ void k_softmax(const int* __restrict__ lens)
{
    int b = blockIdx.x / HEADS, h = blockIdx.x % HEADS;
    int t = threadIdx.x;               // 512
    int L = lens[b];
    __shared__ float red[512];
    float sv = (t < L) ? g_s[((size_t)b * HEADS + h) * T + t] : -3.0e38f;
    red[t] = sv; __syncthreads();
    for (int off = 256; off; off >>= 1) { if (t < off) red[t] = fmaxf(red[t], red[t + off]); __syncthreads(); }
    float m = red[0]; __syncthreads();
    float e = (t < L) ? expf(sv - m) : 0.0f;
    red[t] = e; __syncthreads();
    for (int off = 256; off; off >>= 1) { if (t < off) red[t] += red[t + off]; __syncthreads(); }
    g_A[((size_t)b * HEADS + h) * T + t] = e / red[0];
}

// ---------------- M = A @ Hc  ->  sentence embeddings ---------------
__global__ void k_M(float* __restrict__ out)
{
    int b = blockIdx.x;
    int d = threadIdx.x;               // 512
    __shared__ float As[HEADS * T];
    for (int i = d; i < HEADS * T; i += 512) As[i] = g_A[(size_t)b * HEADS * T + i];
    __syncthreads();
    float acc[HEADS] = {};
    const float* hcb = g_Hc + (size_t)b * T * 512;
    for (int t = 0; t < T; t++) {
        float hc = hcb[(size_t)t * 512 + d];
        #pragma unroll
        for (int h = 0; h < HEADS; h++) acc[h] = fmaf(As[h * T + t], hc, acc[h]);
    }
    #pragma unroll
    for (int h = 0; h < HEADS; h++)
        out[(size_t)b * (HEADS * 2 * H) + h * 512 + d] = acc[h];
}

// ---------------- penalty -------------------------------------------
__global__ void k_penal1()
{
    int b = blockIdx.x;
    int tid = threadIdx.x;             // 256
    __shared__ float As[HEADS * T];
    __shared__ float red[256];
    for (int i = tid; i < HEADS * T; i += 256) As[i] = g_A[(size_t)b * HEADS * T + i];
    __syncthreads();
    float tot = 0.0f;
    for (int h = 0; h < HEADS; h++) {
        for (int g = 0; g < HEADS; g++) {
            if (h == g) continue;
            float p = 0.0f;
            for (int t = tid; t < T; t += 256) p = fmaf(As[h * T + t], As[g * T + t], p);
            red[tid] = p; __syncthreads();
            for (int off = 128; off; off >>= 1) { if (tid < off) red[tid] += red[tid + off]; __syncthreads(); }
            if (tid == 0) tot += red[0] * red[0];
            __syncthreads();
        }
    }
    if (tid == 0) g_pp[b] = tot;
}

__global__ void k_penal2(float* __restrict__ out, int out_size)
{
    __shared__ float red[128];
    red[threadIdx.x] = g_pp[threadIdx.x];
    __syncthreads();
    for (int off = 64; off; off >>= 1) { if (threadIdx.x < off) red[threadIdx.x] += red[threadIdx.x + off]; __syncthreads(); }
    if (threadIdx.x == 0) out[out_size - 1] = red[0] / (float)B;
}

// ---------------- launch --------------------------------------------
extern "C" void kernel_launch(void* const* d_in, const int* in_sizes, int n_in,
                              void* d_out, int out_size)
{
    const int*   word_ids = (const int*)  d_in[0];
    const int*   lens     = (const int*)  d_in[1];
    const float* emb      = (const float*)d_in[2];
    const float* Wihf     = (const float*)d_in[3];
    const float* Whhf     = (const float*)d_in[4];
    const float* bf       = (const float*)d_in[5];
    const float* Wihb     = (const float*)d_in[6];
    const float* Whhb     = (const float*)d_in[7];
    const float* bb       = (const float*)d_in[8];
    const float* Ws1      = (const float*)d_in[9];
    const float* Ws2      = (const float*)d_in[10];
    float* out = (float*)d_out;

    k_init<<<64, 256>>>();
    k_perm<<<1, 128>>>(lens);

    dim3 gP(16, (V + 63) / 64, 2);
    k_P<<<gP, 256>>>(emb, Wihf, bf, Wihb, bb);

    cudaFuncSetAttribute(k_lstm, cudaFuncAttributeMaxDynamicSharedMemorySize, 50304);
    k_lstm<<<128, 256, 50304>>>(Whhf, Whhb, lens, word_ids);

    cudaFuncSetAttribute(k_scores, cudaFuncAttributeMaxDynamicSharedMemorySize, 57600);
    k_scores<<<(B * T) / 32, 512, 57600>>>(Ws1, Ws2);

    k_softmax<<<B * HEADS, 512>>>(lens);
    k_M<<<B, 512>>>(out);
    k_penal1<<<B, 256>>>();
    k_penal2<<<1, 128>>>(out, out_size);
}

// round 16
// speedup vs baseline: 1.5745x; 1.5745x over previous
#include <cuda_runtime.h>
#include <math.h>
#include <stdint.h>

#define B 128
#define T 512
#define E 256
#define H 256
#define DA 25
#define HEADS 5
#define V 2080

typedef unsigned long long ull;

// ---------------- device scratch (static, no allocs) ----------------
__device__ float g_P[(size_t)2 * V * 1024];        // [dir][v][4H]  17MB (L2-resident)
__device__ float g_hstate[2 * 2 * B * H];          // [buf][dir][slot][H]  (slot-indexed)
__device__ float g_Hc[(size_t)B * T * 2 * H];      // [b][t][512]; tail stale-but-finite, masked by A=0
__device__ float g_s[B * HEADS * T];               // [b][h][t]
__device__ float g_A[B * HEADS * T];               // [b][h][t]
__device__ float g_pp[B];
__device__ unsigned g_bar[16];                     // [dir][bg]
__device__ int g_perm[B];                          // rank -> batch (length desc)
__device__ int g_slen[B];                          // rank -> length

// fast, overflow-safe sigmoid/tanh via MUFU.EX2 path (__expf)
__device__ __forceinline__ float sigf(float x) {
    return 1.0f / (1.0f + __expf(-x));
}
__device__ __forceinline__ float tanhfast(float x) {
    float ax = fabsf(x);
    float e = __expf(2.0f * ax);
    float t = 1.0f - 2.0f / (e + 1.0f);
    return copysignf(t, x);
}

__device__ __forceinline__ ull pack2(float lo, float hi) {
    ull r; asm("mov.b64 %0, {%1,%2};" : "=l"(r) : "f"(lo), "f"(hi)); return r;
}
__device__ __forceinline__ void unpack2(ull v, float& lo, float& hi) {
    asm("mov.b64 {%0,%1}, %2;" : "=f"(lo), "=f"(hi) : "l"(v));
}
__device__ __forceinline__ ull fma2(ull a, ull b, ull c) {
    ull d; asm("fma.rn.f32x2 %0, %1, %2, %3;" : "=l"(d) : "l"(a), "l"(b), "l"(c)); return d;
}
__device__ __forceinline__ ull add2(ull a, ull b) {
    ull d; asm("add.rn.f32x2 %0, %1, %2;" : "=l"(d) : "l"(a), "l"(b)); return d;
}

// ---------------- init: zero h buffers + barriers --------------------
__global__ void k_init() {
    size_t i = (size_t)blockIdx.x * blockDim.x + threadIdx.x;
    size_t stride = (size_t)gridDim.x * blockDim.x;
    for (size_t p = i; p < (size_t)2 * 2 * B * H; p += stride) g_hstate[p] = 0.0f;
    if (i < 16) g_bar[i] = 0u;
}

// ---------------- rank batches by length (descending, stable) -------
__global__ void k_perm(const int* __restrict__ lens) {
    __shared__ int Ls[B];
    int i = threadIdx.x;
    Ls[i] = lens[i];
    __syncthreads();
    int Li = Ls[i];
    int rank = 0;
    #pragma unroll 8
    for (int j = 0; j < B; j++) {
        int Lj = Ls[j];
        rank += (Lj > Li) || (Lj == Li && j < i);
    }
    g_perm[rank] = i;
    g_slen[rank] = Li;
}

// ---------------- vocab projection: P[d][v][n] = emb[v] . W_ih[n] + b[n]
// Inner product in f32x2 over j-pairs: Bs pair loads are free (ulonglong2
// from smem), only a-broadcast packs are explicit (alu pipe).
__global__ void k_P(const float* __restrict__ emb,
                    const float* __restrict__ Wf, const float* __restrict__ bf,
                    const float* __restrict__ Wb, const float* __restrict__ bb)
{
    const int d = blockIdx.z;
    const float* __restrict__ Wih  = d ? Wb : Wf;
    const float* __restrict__ bias = d ? bb : bf;
    const int n0 = blockIdx.x * 64;
    const int m0 = blockIdx.y * 64;

    __shared__ float As[16][68];
    __shared__ float Bs[16][68];

    const int tid = threadIdx.x;
    const int r  = tid >> 2, kq = tid & 3;
    const int tx = tid & 15, ty = tid >> 4;
    int v = m0 + r; if (v >= V) v = 0;
    const float* __restrict__ Arow = emb + (size_t)v * E;
    const float* __restrict__ Brow = Wih + (size_t)(n0 + r) * E;

    ull acc2[4][2] = {};

    for (int k0 = 0; k0 < E; k0 += 16) {
        float4 av = *(const float4*)&Arow[k0 + kq * 4];
        float4 bv = *(const float4*)&Brow[k0 + kq * 4];
        As[kq * 4 + 0][r] = av.x; As[kq * 4 + 1][r] = av.y;
        As[kq * 4 + 2][r] = av.z; As[kq * 4 + 3][r] = av.w;
        Bs[kq * 4 + 0][r] = bv.x; Bs[kq * 4 + 1][r] = bv.y;
        Bs[kq * 4 + 2][r] = bv.z; Bs[kq * 4 + 3][r] = bv.w;
        __syncthreads();
        #pragma unroll
        for (int kk = 0; kk < 16; kk++) {
            float4 a = *(const float4*)&As[kk][ty * 4];
            ulonglong2 bp = *(const ulonglong2*)&Bs[kk][tx * 4];   // (b0,b1),(b2,b3)
            ull a0 = pack2(a.x, a.x), a1 = pack2(a.y, a.y);
            ull a2 = pack2(a.z, a.z), a3 = pack2(a.w, a.w);
            acc2[0][0] = fma2(a0, bp.x, acc2[0][0]); acc2[0][1] = fma2(a0, bp.y, acc2[0][1]);
            acc2[1][0] = fma2(a1, bp.x, acc2[1][0]); acc2[1][1] = fma2(a1, bp.y, acc2[1][1]);
            acc2[2][0] = fma2(a2, bp.x, acc2[2][0]); acc2[2][1] = fma2(a2, bp.y, acc2[2][1]);
            acc2[3][0] = fma2(a3, bp.x, acc2[3][0]); acc2[3][1] = fma2(a3, bp.y, acc2[3][1]);
        }
        __syncthreads();
    }

    float b0v = bias[n0 + tx * 4 + 0];
    float b1v = bias[n0 + tx * 4 + 1];
    float b2v = bias[n0 + tx * 4 + 2];
    float b3v = bias[n0 + tx * 4 + 3];
    const size_t pbase = (size_t)d * V * 1024;
    #pragma unroll
    for (int i = 0; i < 4; i++) {
        int m = m0 + ty * 4 + i;
        if (m < V) {
            float x0, x1, x2, x3;
            unpack2(acc2[i][0], x0, x1);
            unpack2(acc2[i][1], x2, x3);
            float4 o;
            o.x = x0 + b0v; o.y = x1 + b1v;
            o.z = x2 + b2v; o.w = x3 + b3v;
            *(float4*)&g_P[pbase + (size_t)m * 1024 + n0 + tx * 4] = o;
        }
    }
}

// ---------------- persistent LSTM recurrence (R12-proven, verbatim) --
// 128 blocks = 2 dirs * 8 j-tiles(32 j) * 8 slot-groups(16 slots); 256 threads.
// Chain = 8 blocks. Slots length-sorted desc, dealt round-robin (rank=8s+bg);
// nact(t) shrinks compute to the live prefix (consistent chain-wide).
// Compute role: warp (kq 0..3, gh 0..1), lane (jcp 0..15, gl 0..1); thread
// owns W rows (g=2gh+gl, j=j0+2jcp, +1) over its 64-k slice in registers.
// h via broadcast LDS.128 from staged smem; kq-reduction via smem Red.
// Epilogue role: thread (slot 0..15, jp 0..15) -> 1 slot, j-pair.
__global__ void __launch_bounds__(256, 1)
k_lstm(const float* __restrict__ Whf, const float* __restrict__ Whb,
       const int* __restrict__ lens, const int* __restrict__ wid)
{
    extern __shared__ float sm[];
    float* Hsh = sm;                       // [16][256] = 4096 floats (16 KB)
    float* Red = sm + 4096;                // [64 rows][132] = 8448 floats
    int*   slen16 = (int*)(sm + 12544);    // [16]

    const int tid = threadIdx.x;
    const int d   = blockIdx.x >> 6;
    const int rem = blockIdx.x & 63;
    const int jb  = rem >> 3, bg = rem & 7;
    const int j0  = jb * 32, b0 = bg * 16;     // b0 = slot base
    const float* __restrict__ Whh = d ? Whb : Whf;
    const float* __restrict__ P   = g_P + (size_t)d * V * 1024;

    // ---- compute-role indices ----
    const int warp = tid >> 5, lane = tid & 31;
    const int kq = warp & 3, gh = warp >> 2;
    const int jcp = lane >> 1, gl = lane & 1;
    const int gc = gh * 2 + gl;

    // ---- W -> registers: 2 j-rows x 64 k, packed over k-pairs ----
    ull w2a[32], w2b[32];
    {
        const float2* wra = (const float2*)(Whh + (size_t)(gc * H + j0 + 2 * jcp)     * H + kq * 64);
        const float2* wrb = (const float2*)(Whh + (size_t)(gc * H + j0 + 2 * jcp + 1) * H + kq * 64);
        #pragma unroll
        for (int i = 0; i < 32; i++) {
            float2 va = __ldg(&wra[i]);
            float2 vb = __ldg(&wrb[i]);
            w2a[i] = pack2(va.x, va.y);
            w2b[i] = pack2(vb.x, vb.y);
        }
    }

    // ---- epilogue-role indices (slot bqs -> global rank 8bqs+bg) ----
    const int jp = tid & 15, bqs = tid >> 4;    // 16 x 16
    const int rankE = 8 * bqs + bg;
    const int bE = g_perm[rankE];               // true batch id
    const int LE = g_slen[rankE];
    const int jcol = j0 + jp * 2;
    if (tid < 16) slen16[tid] = g_slen[8 * tid + bg];
    __syncthreads();
    const int maxlen = slen16[0];
    int nact = 16;

    float c0 = 0.f, c1 = 0.f;
    unsigned* barp = &g_bar[d * 8 + bg];

    for (int t = 0; t < maxlen; t++) {
        // ---- shrink active prefix (sorted desc; identical across chain) ----
        while (nact > 0 && slen16[nact - 1] <= t) nact--;
        const int rowcnt = (nact + 3) & ~3;
        const int bbn = (nact + 1) >> 1;

        // ---- px prefetch (epilogue role; L2-resident P) ----
        float2 px0, px1, px2, px3;
        int pos = 0;
        const bool vE = (t < LE);
        if (vE) {
            pos = d ? (LE - 1 - t) : t;
            const float2* p = (const float2*)(P + (size_t)wid[bE * T + pos] * 1024) + (j0 >> 1) + jp;
            px0 = __ldg(p); px1 = __ldg(p + 128); px2 = __ldg(p + 256); px3 = __ldg(p + 384);
        }

        // ---- wait for all 8 blocks' h(t-1) (fence-free acquire) ----
        if (tid == 0) {
            unsigned target = 8u * (unsigned)t;
            unsigned v;
            do {
                asm volatile("ld.acquire.gpu.global.u32 %0, [%1];" : "=r"(v) : "l"(barp) : "memory");
            } while (v < target);
        }
        __syncthreads();

        // ---- stage live h rows (slot-indexed, from L2) ----
        const int rb = t & 1;
        {
            const float* hsrc = g_hstate + ((size_t)(rb * 2 + d) * B + b0) * H;
            for (int i = tid; i < rowcnt * 64; i += 256) {
                int r = i >> 6, cc = i & 63;
                float4 hv = __ldcg((const float4*)(hsrc + r * H + cc * 4));
                *(float4*)&Hsh[r * 256 + cc * 4] = hv;
            }
        }
        __syncthreads();

        // ---- compute live slots: W in regs (2 j rows), h broadcast ----
        for (int bb = 0; bb < bbn; bb++) {
            const ulonglong2* r0 = (const ulonglong2*)(Hsh + (2 * bb) * 256 + kq * 64);
            const ulonglong2* r1 = (const ulonglong2*)(Hsh + (2 * bb + 1) * 256 + kq * 64);
            ull aA0 = 0, aA1 = 0, aB0 = 0, aB1 = 0;   // slot0/1 x j-even/odd (k-pair lanes)
            #pragma unroll
            for (int k4 = 0; k4 < 16; k4++) {
                ulonglong2 h0 = r0[k4];
                ulonglong2 h1 = r1[k4];
                aA0 = fma2(w2a[2 * k4],     h0.x, aA0);
                aA1 = fma2(w2b[2 * k4],     h0.x, aA1);
                aB0 = fma2(w2a[2 * k4],     h1.x, aB0);
                aB1 = fma2(w2b[2 * k4],     h1.x, aB1);
                aA0 = fma2(w2a[2 * k4 + 1], h0.y, aA0);
                aA1 = fma2(w2b[2 * k4 + 1], h0.y, aA1);
                aB0 = fma2(w2a[2 * k4 + 1], h1.y, aB0);
                aB1 = fma2(w2b[2 * k4 + 1], h1.y, aB1);
            }
            float xA0, yA0, xA1, yA1, xB0, yB0, xB1, yB1;
            unpack2(aA0, xA0, yA0); unpack2(aA1, xA1, yA1);
            unpack2(aB0, xB0, yB0); unpack2(aB1, xB1, yB1);
            // pack (j even, j odd) into one 8B store per slot
            *(ull*)&Red[((2 * bb)     * 4 + gc) * 132 + kq * 32 + jcp * 2] = pack2(xA0 + yA0, xA1 + yA1);
            *(ull*)&Red[((2 * bb + 1) * 4 + gc) * 132 + kq * 32 + jcp * 2] = pack2(xB0 + yB0, xB1 + yB1);
        }
        __syncthreads();

        // ---- epilogue: reduce over kq, gates, publish ----
        const int wb = (t + 1) & 1;
        if (vE) {
            ull ag[4];
            #pragma unroll
            for (int g = 0; g < 4; g++) {
                const float* rr = Red + (size_t)(bqs * 4 + g) * 132 + jp * 2;
                ull v0 = *(const ull*)(rr);
                ull v1 = *(const ull*)(rr + 32);
                ull v2 = *(const ull*)(rr + 64);
                ull v3 = *(const ull*)(rr + 96);
                ag[g] = add2(add2(v0, v1), add2(v2, v3));
            }
            float gi0, gi1, gf0, gf1, gg0, gg1, go0, go1;
            unpack2(ag[0], gi0, gi1); unpack2(ag[1], gf0, gf1);
            unpack2(ag[2], gg0, gg1); unpack2(ag[3], go0, go1);
            float i0 = sigf (gi0 + px0.x), i1 = sigf (gi1 + px0.y);
            float f0 = sigf (gf0 + px1.x), f1 = sigf (gf1 + px1.y);
            float g0 = tanhfast(gg0 + px2.x), g1 = tanhfast(gg1 + px2.y);
            float o0 = sigf (go0 + px3.x), o1 = sigf (go1 + px3.y);
            c0 = f0 * c0 + i0 * g0;
            c1 = f1 * c1 + i1 * g1;
            float2 hv; hv.x = o0 * tanhfast(c0); hv.y = o1 * tanhfast(c1);
            // slot-indexed internal state; batch-indexed Hc output
            *(float2*)&g_hstate[((size_t)(wb * 2 + d) * B + b0 + bqs) * H + jcol] = hv;
            *(float2*)&g_Hc[((size_t)bE * T + pos) * (2 * H) + d * H + jcol] = hv;
        }

        // ---- arrive (fence-free release; bar.sync orders prior stores) ----
        __syncthreads();
        if (tid == 0)
            asm volatile("red.release.gpu.global.add.u32 [%0], %1;" :: "l"(barp), "r"(1u) : "memory");
    }
}

// ---------------- attention scores: s = tanh(Hc W_s1^T) W_s2^T ------
__global__ void k_scores(const float* __restrict__ Ws1, const float* __restrict__ Ws2)
{
    extern __shared__ float s2[];
    float* Ws  = s2;            // 25*512 = 12800
    float* raw = s2 + 12800;    // 32*25 = 800
    float* usm = s2 + 13600;    // 800

    const int tid = threadIdx.x;
    const int b  = blockIdx.x >> 4;
    const int t0 = (blockIdx.x & 15) * 32;

    for (int i = tid; i < 12800; i += 512) Ws[i] = Ws1[i];
    __syncthreads();

    const int wp = tid >> 5, lane = tid & 31;
    float acc0[DA] = {}, acc1[DA] = {};
    const float* hc0 = g_Hc + ((size_t)b * T + t0 + wp * 2) * 512;
    #pragma unroll 4
    for (int kk = 0; kk < 16; kk++) {
        int k = lane + kk * 32;
        float h0 = hc0[k];
        float h1 = hc0[512 + k];
        #pragma unroll
        for (int a = 0; a < DA; a++) {
            float w = Ws[a * 512 + k];
            acc0[a] = fmaf(h0, w, acc0[a]);
            acc1[a] = fmaf(h1, w, acc1[a]);
        }
    }
    #pragma unroll
    for (int a = 0; a < DA; a++) {
        float v0 = acc0[a], v1 = acc1[a];
        #pragma unroll
        for (int off = 16; off; off >>= 1) {
            v0 += __shfl_xor_sync(0xffffffffu, v0, off);
            v1 += __shfl_xor_sync(0xffffffffu, v1, off);
        }
        if (lane == 0) {
            raw[(wp * 2 + 0) * DA + a] = v0;
            raw[(wp * 2 + 1) * DA + a] = v1;
        }
    }
    __syncthreads();
    for (int i = tid; i < 32 * DA; i += 512) usm[i] = tanhf(raw[i]);
    __syncthreads();
    if (tid < 32 * HEADS) {
        int r = tid / HEADS, h = tid % HEADS;
        float s = 0.f;
        #pragma unroll
        for (int a = 0; a < DA; a++) s = fmaf(usm[r * DA + a], __ldg(&Ws2[h * DA + a]), s);
        g_s[((size_t)b * HEADS + h) * T + t0 + r] = s;
    }
}

// ---------------- masked softmax over time, per (b,head) ------------
__global__ void k_softmax(const int* __restrict__ lens)
{
    int b = blockIdx.x / HEADS, h = blockIdx.x % HEADS;
    int t = threadIdx.x;               // 512
    int L = lens[b];
    __shared__ float red[512];
    float sv = (t < L) ? g_s[((size_t)b * HEADS + h) * T + t] : -3.0e38f;
    red[t] = sv; __syncthreads();
    for (int off = 256; off; off >>= 1) { if (t < off) red[t] = fmaxf(red[t], red[t + off]); __syncthreads(); }
    float m = red[0]; __syncthreads();
    float e = (t < L) ? expf(sv - m) : 0.0f;
    red[t] = e; __syncthreads();
    for (int off = 256; off; off >>= 1) { if (t < off) red[t] += red[t + off]; __syncthreads(); }
    g_A[((size_t)b * HEADS + h) * T + t] = e / red[0];
}

// ---------------- M = A @ Hc  ->  sentence embeddings ---------------
__global__ void k_M(float* __restrict__ out)
{
    int b = blockIdx.x;
    int d = threadIdx.x;               // 512
    __shared__ float As[HEADS * T];
    for (int i = d; i < HEADS * T; i += 512) As[i] = g_A[(size_t)b * HEADS * T + i];
    __syncthreads();
    float acc[HEADS] = {};
    const float* hcb = g_Hc + (size_t)b * T * 512;
    for (int t = 0; t < T; t++) {
        float hc = hcb[(size_t)t * 512 + d];
        #pragma unroll
        for (int h = 0; h < HEADS; h++) acc[h] = fmaf(As[h * T + t], hc, acc[h]);
    }
    #pragma unroll
    for (int h = 0; h < HEADS; h++)
        out[(size_t)b * (HEADS * 2 * H) + h * 512 + d] = acc[h];
}

// ---------------- penalty -------------------------------------------
__global__ void k_penal1()
{
    int b = blockIdx.x;
    int tid = threadIdx.x;             // 256
    __shared__ float As[HEADS * T];
    __shared__ float red[256];
    for (int i = tid; i < HEADS * T; i += 256) As[i] = g_A[(size_t)b * HEADS * T + i];
    __syncthreads();
    float tot = 0.0f;
    for (int h = 0; h < HEADS; h++) {
        for (int g = 0; g < HEADS; g++) {
            if (h == g) continue;
            float p = 0.0f;
            for (int t = tid; t < T; t += 256) p = fmaf(As[h * T + t], As[g * T + t], p);
            red[tid] = p; __syncthreads();
            for (int off = 128; off; off >>= 1) { if (tid < off) red[tid] += red[tid + off]; __syncthreads(); }
            if (tid == 0) tot += red[0] * red[0];
            __syncthreads();
        }
    }
    if (tid == 0) g_pp[b] = tot;
}

__global__ void k_penal2(float* __restrict__ out, int out_size)
{
    __shared__ float red[128];
    red[threadIdx.x] = g_pp[threadIdx.x];
    __syncthreads();
    for (int off = 64; off; off >>= 1) { if (threadIdx.x < off) red[threadIdx.x] += red[threadIdx.x + off]; __syncthreads(); }
    if (threadIdx.x == 0) out[out_size - 1] = red[0] / (float)B;
}

// ---------------- launch --------------------------------------------
extern "C" void kernel_launch(void* const* d_in, const int* in_sizes, int n_in,
                              void* d_out, int out_size)
{
    const int*   word_ids = (const int*)  d_in[0];
    const int*   lens     = (const int*)  d_in[1];
    const float* emb      = (const float*)d_in[2];
    const float* Wihf     = (const float*)d_in[3];
    const float* Whhf     = (const float*)d_in[4];
    const float* bf       = (const float*)d_in[5];
    const float* Wihb     = (const float*)d_in[6];
    const float* Whhb     = (const float*)d_in[7];
    const float* bb       = (const float*)d_in[8];
    const float* Ws1      = (const float*)d_in[9];
    const float* Ws2      = (const float*)d_in[10];
    float* out = (float*)d_out;

    k_init<<<64, 256>>>();
    k_perm<<<1, 128>>>(lens);

    dim3 gP(16, (V + 63) / 64, 2);
    k_P<<<gP, 256>>>(emb, Wihf, bf, Wihb, bb);

    cudaFuncSetAttribute(k_lstm, cudaFuncAttributeMaxDynamicSharedMemorySize, 50304);
    k_lstm<<<128, 256, 50304>>>(Whhf, Whhb, lens, word_ids);

    cudaFuncSetAttribute(k_scores, cudaFuncAttributeMaxDynamicSharedMemorySize, 57600);
    k_scores<<<(B * T) / 32, 512, 57600>>>(Ws1, Ws2);

    k_softmax<<<B * HEADS, 512>>>(lens);
    k_M<<<B, 512>>>(out);
    k_penal1<<<B, 256>>>();
    k_penal2<<<1, 128>>>(out, out_size);
}

// round 17
// speedup vs baseline: 1.6411x; 1.0423x over previous
#include <cuda_runtime.h>
#include <math.h>
#include <stdint.h>

#define B 128
#define T 512
#define E 256
#define H 256
#define DA 25
#define HEADS 5
#define V 2080

typedef unsigned long long ull;

// ---------------- device scratch (static, no allocs) ----------------
__device__ float g_P[(size_t)2 * V * 1024];        // [dir][v][4H]  17MB (L2-resident)
__device__ float g_hstate[2 * 2 * B * H];          // [buf][dir][slot][H]  (slot-indexed)
__device__ float g_Hc[(size_t)B * T * 2 * H];      // [b][t][512]; tail stale-but-finite, masked by A=0
__device__ float g_s[B * HEADS * T];               // [b][h][t]
__device__ float g_A[B * HEADS * T];               // [b][h][t]
__device__ float g_pp[B];
__device__ unsigned g_bar[16];                     // [dir][bg]
__device__ int g_perm[B];                          // rank -> batch (length desc)
__device__ int g_slen[B];                          // rank -> length

// fast, overflow-safe sigmoid/tanh via MUFU.EX2 path (__expf)
__device__ __forceinline__ float sigf(float x) {
    return 1.0f / (1.0f + __expf(-x));
}
__device__ __forceinline__ float tanhfast(float x) {
    float ax = fabsf(x);
    float e = __expf(2.0f * ax);
    float t = 1.0f - 2.0f / (e + 1.0f);
    return copysignf(t, x);
}

__device__ __forceinline__ ull pack2(float lo, float hi) {
    ull r; asm("mov.b64 %0, {%1,%2};" : "=l"(r) : "f"(lo), "f"(hi)); return r;
}
__device__ __forceinline__ void unpack2(ull v, float& lo, float& hi) {
    asm("mov.b64 {%0,%1}, %2;" : "=f"(lo), "=f"(hi) : "l"(v));
}
__device__ __forceinline__ ull fma2(ull a, ull b, ull c) {
    ull d; asm("fma.rn.f32x2 %0, %1, %2, %3;" : "=l"(d) : "l"(a), "l"(b), "l"(c)); return d;
}
__device__ __forceinline__ ull add2(ull a, ull b) {
    ull d; asm("add.rn.f32x2 %0, %1, %2;" : "=l"(d) : "l"(a), "l"(b)); return d;
}

// ---------------- init: zero h buffers + barriers --------------------
__global__ void k_init() {
    size_t i = (size_t)blockIdx.x * blockDim.x + threadIdx.x;
    size_t stride = (size_t)gridDim.x * blockDim.x;
    for (size_t p = i; p < (size_t)2 * 2 * B * H; p += stride) g_hstate[p] = 0.0f;
    if (i < 16) g_bar[i] = 0u;
}

// ---------------- rank batches by length (descending, stable) -------
__global__ void k_perm(const int* __restrict__ lens) {
    __shared__ int Ls[B];
    int i = threadIdx.x;
    Ls[i] = lens[i];
    __syncthreads();
    int Li = Ls[i];
    int rank = 0;
    #pragma unroll 8
    for (int j = 0; j < B; j++) {
        int Lj = Ls[j];
        rank += (Lj > Li) || (Lj == Li && j < i);
    }
    g_perm[rank] = i;
    g_slen[rank] = Li;
}

// ---------------- vocab projection: P[d][v][n] = emb[v] . W_ih[n] + b[n]
// Inner product in f32x2 over j-pairs (R16-proven).
__global__ void k_P(const float* __restrict__ emb,
                    const float* __restrict__ Wf, const float* __restrict__ bf,
                    const float* __restrict__ Wb, const float* __restrict__ bb)
{
    const int d = blockIdx.z;
    const float* __restrict__ Wih  = d ? Wb : Wf;
    const float* __restrict__ bias = d ? bb : bf;
    const int n0 = blockIdx.x * 64;
    const int m0 = blockIdx.y * 64;

    __shared__ float As[16][68];
    __shared__ float Bs[16][68];

    const int tid = threadIdx.x;
    const int r  = tid >> 2, kq = tid & 3;
    const int tx = tid & 15, ty = tid >> 4;
    int v = m0 + r; if (v >= V) v = 0;
    const float* __restrict__ Arow = emb + (size_t)v * E;
    const float* __restrict__ Brow = Wih + (size_t)(n0 + r) * E;

    ull acc2[4][2] = {};

    for (int k0 = 0; k0 < E; k0 += 16) {
        float4 av = *(const float4*)&Arow[k0 + kq * 4];
        float4 bv = *(const float4*)&Brow[k0 + kq * 4];
        As[kq * 4 + 0][r] = av.x; As[kq * 4 + 1][r] = av.y;
        As[kq * 4 + 2][r] = av.z; As[kq * 4 + 3][r] = av.w;
        Bs[kq * 4 + 0][r] = bv.x; Bs[kq * 4 + 1][r] = bv.y;
        Bs[kq * 4 + 2][r] = bv.z; Bs[kq * 4 + 3][r] = bv.w;
        __syncthreads();
        #pragma unroll
        for (int kk = 0; kk < 16; kk++) {
            float4 a = *(const float4*)&As[kk][ty * 4];
            ulonglong2 bp = *(const ulonglong2*)&Bs[kk][tx * 4];
            ull a0 = pack2(a.x, a.x), a1 = pack2(a.y, a.y);
            ull a2 = pack2(a.z, a.z), a3 = pack2(a.w, a.w);
            acc2[0][0] = fma2(a0, bp.x, acc2[0][0]); acc2[0][1] = fma2(a0, bp.y, acc2[0][1]);
            acc2[1][0] = fma2(a1, bp.x, acc2[1][0]); acc2[1][1] = fma2(a1, bp.y, acc2[1][1]);
            acc2[2][0] = fma2(a2, bp.x, acc2[2][0]); acc2[2][1] = fma2(a2, bp.y, acc2[2][1]);
            acc2[3][0] = fma2(a3, bp.x, acc2[3][0]); acc2[3][1] = fma2(a3, bp.y, acc2[3][1]);
        }
        __syncthreads();
    }

    float b0v = bias[n0 + tx * 4 + 0];
    float b1v = bias[n0 + tx * 4 + 1];
    float b2v = bias[n0 + tx * 4 + 2];
    float b3v = bias[n0 + tx * 4 + 3];
    const size_t pbase = (size_t)d * V * 1024;
    #pragma unroll
    for (int i = 0; i < 4; i++) {
        int m = m0 + ty * 4 + i;
        if (m < V) {
            float x0, x1, x2, x3;
            unpack2(acc2[i][0], x0, x1);
            unpack2(acc2[i][1], x2, x3);
            float4 o;
            o.x = x0 + b0v; o.y = x1 + b1v;
            o.z = x2 + b2v; o.w = x3 + b3v;
            *(float4*)&g_P[pbase + (size_t)m * 1024 + n0 + tx * 4] = o;
        }
    }
}

// ---------------- persistent LSTM recurrence (dual-resident chains) --
// 256 blocks = 2 dirs * 16 j-tiles(16 j) * 8 slot-groups(16 slots);
// 128 threads, 2 blocks/SM: a barrier-stalled chain block overlaps with a
// computing block of a DIFFERENT chain on the same SM.
// Chain = 16 blocks (one per j-tile) synced via one L2 counter (R12 form).
// Slots length-sorted desc, dealt round-robin (rank = 8s+bg); nact(t)
// shrinks compute to the live prefix (identical chain-wide).
// Compute role: warp = kq (0..3); lane = (jcp 0..7, g 0..3); thread owns
// W rows (g, j0+2jcp / +1) over its 64-k slice in regs (2x32 f32x2).
// h via broadcast LDS.128 from staged smem; kq-reduction via smem Red.
// Epilogue role: thread (slot 0..15, jp 0..7) -> 1 slot, j-pair.
__global__ void __launch_bounds__(128, 2)
k_lstm(const float* __restrict__ Whf, const float* __restrict__ Whb,
       const int* __restrict__ lens, const int* __restrict__ wid)
{
    extern __shared__ float sm[];
    float* Hsh = sm;                       // [16][256] = 4096 floats (16 KB)
    float* Red = sm + 4096;                // [64 rows][68] = 4352 floats
    int*   slen16 = (int*)(sm + 8448);     // [16]

    const int tid = threadIdx.x;
    const int d   = blockIdx.x >> 7;
    const int rem = blockIdx.x & 127;
    const int jb  = rem & 15, bg = rem >> 4;
    const int j0  = jb * 16, b0 = bg * 16;     // b0 = slot base
    const float* __restrict__ Whh = d ? Whb : Whf;
    const float* __restrict__ P   = g_P + (size_t)d * V * 1024;

    // ---- compute-role indices ----
    const int kq = tid >> 5, lane = tid & 31;
    const int jcp = lane >> 2, g = lane & 3;

    // ---- W -> registers: 2 j-rows (a j-pair) x 64 k, packed over k-pairs ----
    ull w2a[32], w2b[32];
    {
        const float2* wra = (const float2*)(Whh + (size_t)(g * H + j0 + 2 * jcp)     * H + kq * 64);
        const float2* wrb = (const float2*)(Whh + (size_t)(g * H + j0 + 2 * jcp + 1) * H + kq * 64);
        #pragma unroll
        for (int i = 0; i < 32; i++) {
            float2 va = __ldg(&wra[i]);
            float2 vb = __ldg(&wrb[i]);
            w2a[i] = pack2(va.x, va.y);
            w2b[i] = pack2(vb.x, vb.y);
        }
    }

    // ---- epilogue-role indices (slot bqs -> global rank 8bqs+bg) ----
    const int jp = tid & 7, bqs = tid >> 3;    // 16 slots x 8 j-pairs
    const int rankE = 8 * bqs + bg;
    const int bE = g_perm[rankE];              // true batch id
    const int LE = g_slen[rankE];
    const int jcol = j0 + jp * 2;
    if (tid < 16) slen16[tid] = g_slen[8 * tid + bg];
    __syncthreads();
    const int maxlen = slen16[0];
    int nact = 16;

    float c0 = 0.f, c1 = 0.f;
    unsigned* barp = &g_bar[d * 8 + bg];

    for (int t = 0; t < maxlen; t++) {
        // ---- shrink active prefix (sorted desc; identical across chain) ----
        while (nact > 0 && slen16[nact - 1] <= t) nact--;
        const int rowcnt = (nact + 3) & ~3;
        const int bbn = (nact + 1) >> 1;

        // ---- px prefetch (epilogue role; L2-resident P) ----
        float2 px0, px1, px2, px3;
        int pos = 0;
        const bool vE = (t < LE);
        if (vE) {
            pos = d ? (LE - 1 - t) : t;
            const float2* p = (const float2*)(P + (size_t)wid[bE * T + pos] * 1024) + (j0 >> 1) + jp;
            px0 = __ldg(p); px1 = __ldg(p + 128); px2 = __ldg(p + 256); px3 = __ldg(p + 384);
        }

        // ---- wait for all 16 blocks' h(t-1) (fence-free acquire) ----
        if (tid == 0) {
            unsigned target = 16u * (unsigned)t;
            unsigned v;
            do {
                asm volatile("ld.acquire.gpu.global.u32 %0, [%1];" : "=r"(v) : "l"(barp) : "memory");
            } while (v < target);
        }
        __syncthreads();

        // ---- stage live h rows (slot-indexed, from L2) ----
        const int rb = t & 1;
        {
            const float* hsrc = g_hstate + ((size_t)(rb * 2 + d) * B + b0) * H;
            for (int i = tid; i < rowcnt * 64; i += 128) {
                int r = i >> 6, cc = i & 63;
                float4 hv = __ldcg((const float4*)(hsrc + r * H + cc * 4));
                *(float4*)&Hsh[r * 256 + cc * 4] = hv;
            }
        }
        __syncthreads();

        // ---- compute live slots: W in regs (j-pair), h broadcast ----
        for (int bb = 0; bb < bbn; bb++) {
            const ulonglong2* r0 = (const ulonglong2*)(Hsh + (2 * bb) * 256 + kq * 64);
            const ulonglong2* r1 = (const ulonglong2*)(Hsh + (2 * bb + 1) * 256 + kq * 64);
            ull aA0 = 0, aA1 = 0, aB0 = 0, aB1 = 0;   // slot0/1 x j-even/odd (k-pair lanes)
            #pragma unroll
            for (int k4 = 0; k4 < 16; k4++) {
                ulonglong2 h0 = r0[k4];
                ulonglong2 h1 = r1[k4];
                aA0 = fma2(w2a[2 * k4],     h0.x, aA0);
                aA1 = fma2(w2b[2 * k4],     h0.x, aA1);
                aB0 = fma2(w2a[2 * k4],     h1.x, aB0);
                aB1 = fma2(w2b[2 * k4],     h1.x, aB1);
                aA0 = fma2(w2a[2 * k4 + 1], h0.y, aA0);
                aA1 = fma2(w2b[2 * k4 + 1], h0.y, aA1);
                aB0 = fma2(w2a[2 * k4 + 1], h1.y, aB0);
                aB1 = fma2(w2b[2 * k4 + 1], h1.y, aB1);
            }
            float xA0, yA0, xA1, yA1, xB0, yB0, xB1, yB1;
            unpack2(aA0, xA0, yA0); unpack2(aA1, xA1, yA1);
            unpack2(aB0, xB0, yB0); unpack2(aB1, xB1, yB1);
            // pack (j even, j odd) into one 8B store per slot
            *(ull*)&Red[((2 * bb)     * 4 + g) * 68 + kq * 16 + jcp * 2] = pack2(xA0 + yA0, xA1 + yA1);
            *(ull*)&Red[((2 * bb + 1) * 4 + g) * 68 + kq * 16 + jcp * 2] = pack2(xB0 + yB0, xB1 + yB1);
        }
        __syncthreads();

        // ---- epilogue: reduce over kq, gates, publish ----
        const int wb = (t + 1) & 1;
        if (vE) {
            ull ag[4];
            #pragma unroll
            for (int gg = 0; gg < 4; gg++) {
                const float* rr = Red + (size_t)(bqs * 4 + gg) * 68 + jp * 2;
                ull v0 = *(const ull*)(rr);
                ull v1 = *(const ull*)(rr + 16);
                ull v2 = *(const ull*)(rr + 32);
                ull v3 = *(const ull*)(rr + 48);
                ag[gg] = add2(add2(v0, v1), add2(v2, v3));
            }
            float gi0, gi1, gf0, gf1, gg0, gg1, go0, go1;
            unpack2(ag[0], gi0, gi1); unpack2(ag[1], gf0, gf1);
            unpack2(ag[2], gg0, gg1); unpack2(ag[3], go0, go1);
            float i0 = sigf (gi0 + px0.x), i1 = sigf (gi1 + px0.y);
            float f0 = sigf (gf0 + px1.x), f1 = sigf (gf1 + px1.y);
            float g0 = tanhfast(gg0 + px2.x), g1 = tanhfast(gg1 + px2.y);
            float o0 = sigf (go0 + px3.x), o1 = sigf (go1 + px3.y);
            c0 = f0 * c0 + i0 * g0;
            c1 = f1 * c1 + i1 * g1;
            float2 hv; hv.x = o0 * tanhfast(c0); hv.y = o1 * tanhfast(c1);
            // slot-indexed internal state; batch-indexed Hc output
            *(float2*)&g_hstate[((size_t)(wb * 2 + d) * B + b0 + bqs) * H + jcol] = hv;
            *(float2*)&g_Hc[((size_t)bE * T + pos) * (2 * H) + d * H + jcol] = hv;
        }

        // ---- arrive (fence-free release; bar.sync orders prior stores) ----
        __syncthreads();
        if (tid == 0)
            asm volatile("red.release.gpu.global.add.u32 [%0], %1;" :: "l"(barp), "r"(1u) : "memory");
    }
}

// ---------------- attention scores: s = tanh(Hc W_s1^T) W_s2^T ------
__global__ void k_scores(const float* __restrict__ Ws1, const float* __restrict__ Ws2)
{
    extern __shared__ float s2[];
    float* Ws  = s2;            // 25*512 = 12800
    float* raw = s2 + 12800;    // 32*25 = 800
    float* usm = s2 + 13600;    // 800

    const int tid = threadIdx.x;
    const int b  = blockIdx.x >> 4;
    const int t0 = (blockIdx.x & 15) * 32;

    for (int i = tid; i < 12800; i += 512) Ws[i] = Ws1[i];
    __syncthreads();

    const int wp = tid >> 5, lane = tid & 31;
    float acc0[DA] = {}, acc1[DA] = {};
    const float* hc0 = g_Hc + ((size_t)b * T + t0 + wp * 2) * 512;
    #pragma unroll 4
    for (int kk = 0; kk < 16; kk++) {
        int k = lane + kk * 32;
        float h0 = hc0[k];
        float h1 = hc0[512 + k];
        #pragma unroll
        for (int a = 0; a < DA; a++) {
            float w = Ws[a * 512 + k];
            acc0[a] = fmaf(h0, w, acc0[a]);
            acc1[a] = fmaf(h1, w, acc1[a]);
        }
    }
    #pragma unroll
    for (int a = 0; a < DA; a++) {
        float v0 = acc0[a], v1 = acc1[a];
        #pragma unroll
        for (int off = 16; off; off >>= 1) {
            v0 += __shfl_xor_sync(0xffffffffu, v0, off);
            v1 += __shfl_xor_sync(0xffffffffu, v1, off);
        }
        if (lane == 0) {
            raw[(wp * 2 + 0) * DA + a] = v0;
            raw[(wp * 2 + 1) * DA + a] = v1;
        }
    }
    __syncthreads();
    for (int i = tid; i < 32 * DA; i += 512) usm[i] = tanhf(raw[i]);
    __syncthreads();
    if (tid < 32 * HEADS) {
        int r = tid / HEADS, h = tid % HEADS;
        float s = 0.f;
        #pragma unroll
        for (int a = 0; a < DA; a++) s = fmaf(usm[r * DA + a], __ldg(&Ws2[h * DA + a]), s);
        g_s[((size_t)b * HEADS + h) * T + t0 + r] = s;
    }
}

// ---------------- masked softmax over time, per (b,head) ------------
__global__ void k_softmax(const int* __restrict__ lens)
{
    int b = blockIdx.x / HEADS, h = blockIdx.x % HEADS;
    int t = threadIdx.x;               // 512
    int L = lens[b];
    __shared__ float red[512];
    float sv = (t < L) ? g_s[((size_t)b * HEADS + h) * T + t] : -3.0e38f;
    red[t] = sv; __syncthreads();
    for (int off = 256; off; off >>= 1) { if (t < off) red[t] = fmaxf(red[t], red[t + off]); __syncthreads(); }
    float m = red[0]; __syncthreads();
    float e = (t < L) ? expf(sv - m) : 0.0f;
    red[t] = e; __syncthreads();
    for (int off = 256; off; off >>= 1) { if (t < off) red[t] += red[t + off]; __syncthreads(); }
    g_A[((size_t)b * HEADS + h) * T + t] = e / red[0];
}

// ---------------- M = A @ Hc  ->  sentence embeddings ---------------
__global__ void k_M(float* __restrict__ out)
{
    int b = blockIdx.x;
    int d = threadIdx.x;               // 512
    __shared__ float As[HEADS * T];
    for (int i = d; i < HEADS * T; i += 512) As[i] = g_A[(size_t)b * HEADS * T + i];
    __syncthreads();
    float acc[HEADS] = {};
    const float* hcb = g_Hc + (size_t)b * T * 512;
    for (int t = 0; t < T; t++) {
        float hc = hcb[(size_t)t * 512 + d];
        #pragma unroll
        for (int h = 0; h < HEADS; h++) acc[h] = fmaf(As[h * T + t], hc, acc[h]);
    }
    #pragma unroll
    for (int h = 0; h < HEADS; h++)
        out[(size_t)b * (HEADS * 2 * H) + h * 512 + d] = acc[h];
}

// ---------------- penalty -------------------------------------------
__global__ void k_penal1()
{
    int b = blockIdx.x;
    int tid = threadIdx.x;             // 256
    __shared__ float As[HEADS * T];
    __shared__ float red[256];
    for (int i = tid; i < HEADS * T; i += 256) As[i] = g_A[(size_t)b * HEADS * T + i];
    __syncthreads();
    float tot = 0.0f;
    for (int h = 0; h < HEADS; h++) {
        for (int g = 0; g < HEADS; g++) {
            if (h == g) continue;
            float p = 0.0f;
            for (int t = tid; t < T; t += 256) p = fmaf(As[h * T + t], As[g * T + t], p);
            red[tid] = p; __syncthreads();
            for (int off = 128; off; off >>= 1) { if (tid < off) red[tid] += red[tid + off]; __syncthreads(); }
            if (tid == 0) tot += red[0] * red[0];
            __syncthreads();
        }
    }
    if (tid == 0) g_pp[b] = tot;
}

__global__ void k_penal2(float* __restrict__ out, int out_size)
{
    __shared__ float red[128];
    red[threadIdx.x] = g_pp[threadIdx.x];
    __syncthreads();
    for (int off = 64; off; off >>= 1) { if (threadIdx.x < off) red[threadIdx.x] += red[threadIdx.x + off]; __syncthreads(); }
    if (threadIdx.x == 0) out[out_size - 1] = red[0] / (float)B;
}

// ---------------- launch --------------------------------------------
extern "C" void kernel_launch(void* const* d_in, const int* in_sizes, int n_in,
                              void* d_out, int out_size)
{
    const int*   word_ids = (const int*)  d_in[0];
    const int*   lens     = (const int*)  d_in[1];
    const float* emb      = (const float*)d_in[2];
    const float* Wihf     = (const float*)d_in[3];
    const float* Whhf     = (const float*)d_in[4];
    const float* bf       = (const float*)d_in[5];
    const float* Wihb     = (const float*)d_in[6];
    const float* Whhb     = (const float*)d_in[7];
    const float* bb       = (const float*)d_in[8];
    const float* Ws1      = (const float*)d_in[9];
    const float* Ws2      = (const float*)d_in[10];
    float* out = (float*)d_out;

    k_init<<<64, 256>>>();
    k_perm<<<1, 128>>>(lens);

    dim3 gP(16, (V + 63) / 64, 2);
    k_P<<<gP, 256>>>(emb, Wihf, bf, Wihb, bb);

    cudaFuncSetAttribute(k_lstm, cudaFuncAttributeMaxDynamicSharedMemorySize, 33856);
    k_lstm<<<256, 128, 33856>>>(Whhf, Whhb, lens, word_ids);

    cudaFuncSetAttribute(k_scores, cudaFuncAttributeMaxDynamicSharedMemorySize, 57600);
    k_scores<<<(B * T) / 32, 512, 57600>>>(Ws1, Ws2);

    k_softmax<<<B * HEADS, 512>>>(lens);
    k_M<<<B, 512>>>(out);
    k_penal1<<<B, 256>>>();
    k_penal2<<<1, 128>>>(out, out_size);
}